// round 11
// baseline (speedup 1.0000x reference)
#include <cuda_runtime.h>
#include <cstdint>

// ---------------- problem constants ----------------
#define SQ    4096          // sequence length
#define EMBD  256
#define HDIRD 256           // HID/2
#define NG    1024          // 4*HDIR
#define TAGS  10
#define NEGV  -10000.0f
#define CL    8             // fallback cluster size
#define CL16  16            // preferred cluster size
#define HPAD  132           // padded half stride in floats (128+4 -> halves in different banks)
#define HBSTR 264           // one buffer = 2 halves = 264 floats

// ---------------- scratch (device globals; no dynamic alloc) ----------------
__device__ float g_x[SQ * EMBD];              // gathered embeddings   4 MB
__device__ float g_xw[2][SQ * NG];            // input-gate precompute 32 MB
__device__ float g_h[2][SQ * HDIRD];          // hidden states         8 MB
__device__ float g_feats[SQ * TAGS];          // CRF emission feats

// ---------------- helpers ----------------
__device__ __forceinline__ uint32_t smem_u32(const void* p) {
    return (uint32_t)__cvta_generic_to_shared(p);
}
__device__ __forceinline__ uint32_t mapa_u32(uint32_t laddr, uint32_t rank) {
    uint32_t rem;
    asm("mapa.shared::cluster.u32 %0, %1, %2;" : "=r"(rem) : "r"(laddr), "r"(rank));
    return rem;
}
// remote store with completion tx delivered to the DESTINATION CTA's mbarrier
__device__ __forceinline__ void st_async_f32(uint32_t raddr, float v, uint32_t rmbar) {
    asm volatile(
        "st.async.shared::cluster.mbarrier::complete_tx::bytes.b32 [%0], %1, [%2];"
        :: "r"(raddr), "r"(__float_as_uint(v)), "r"(rmbar) : "memory");
}
__device__ __forceinline__ void mbar_init(uint32_t a, uint32_t cnt) {
    asm volatile("mbarrier.init.shared.b64 [%0], %1;" :: "r"(a), "r"(cnt) : "memory");
}
__device__ __forceinline__ void mbar_expect_tx(uint32_t a, uint32_t bytes) {
    asm volatile("mbarrier.arrive.expect_tx.shared.b64 _, [%0], %1;"
                 :: "r"(a), "r"(bytes) : "memory");
}
// exact known-good wait form from ptx_helpers.cuh (local CTA scope)
__device__ __forceinline__ void mbar_wait(uint32_t a, uint32_t par) {
    uint32_t done;
    asm volatile(
        "{\n\t.reg .pred p;\n\t"
        "mbarrier.try_wait.parity.acquire.cta.shared::cta.b64 p, [%1], %2;\n\t"
        "selp.b32 %0, 1, 0, p;\n\t}"
        : "=r"(done) : "r"(a), "r"(par) : "memory");
    if (!done) {
        asm volatile(
            "{\n\t.reg .pred P1;\n\t"
            "WAIT_LOOP_%=:\n\t"
            "mbarrier.try_wait.parity.acquire.cta.shared::cta.b64 P1, [%0], %1, 0x989680;\n\t"
            "@P1 bra.uni WAIT_DONE_%=;\n\t"
            "bra.uni WAIT_LOOP_%=;\n\t"
            "WAIT_DONE_%=:\n\t}"
            :: "r"(a), "r"(par) : "memory");
    }
}
#define CLUSTER_SYNC_() do {                                                   \
    asm volatile("barrier.cluster.arrive.aligned;" ::: "memory");              \
    asm volatile("barrier.cluster.wait.aligned;"   ::: "memory");              \
} while (0)

__device__ __forceinline__ void fma2(unsigned long long& d,
                                     unsigned long long a, unsigned long long b) {
    asm("fma.rn.f32x2 %0, %1, %2, %0;" : "+l"(d) : "l"(a), "l"(b));
}

__device__ __forceinline__ float sigm_f(float x) {
    return 1.0f / (1.0f + __expf(-x));
}
__device__ __forceinline__ float tanh_f(float x) {
    float e = __expf(-2.0f * fabsf(x));
    float r = (1.0f - e) / (1.0f + e);
    return copysignf(r, x);
}

// ---------------- kernel 1: embedding gather ----------------
__global__ void gather_k(const int* __restrict__ sent, const float* __restrict__ emb) {
    int gid = blockIdx.x * blockDim.x + threadIdx.x;  // over SQ*64 float4
    int row = gid >> 6;
    int c   = gid & 63;
    ((float4*)g_x)[row * 64 + c] =
        ((const float4*)emb)[(size_t)sent[row] * 64 + c];
}

// ---------------- kernel 2: xw = x @ Wih^T + (bih+bhh), both directions ----------------
__global__ void xw_gemm_k(const float* __restrict__ Wf, const float* __restrict__ Wb,
                          const float* __restrict__ bihf, const float* __restrict__ bhhf,
                          const float* __restrict__ bihb, const float* __restrict__ bhhb) {
    int d = blockIdx.z;
    const float* W  = d ? Wb : Wf;
    const float* b1 = d ? bihb : bihf;
    const float* b2 = d ? bhhb : bhhf;

    __shared__ float As[32][65];
    __shared__ float Bs[32][65];

    int s0 = blockIdx.x * 64;
    int j0 = blockIdx.y * 64;
    int tid = threadIdx.x;
    int tx = tid & 15, ty = tid >> 4;

    float acc[4][4];
#pragma unroll
    for (int i = 0; i < 4; i++)
#pragma unroll
        for (int j = 0; j < 4; j++) acc[i][j] = 0.0f;

    for (int k0 = 0; k0 < EMBD; k0 += 32) {
#pragma unroll
        for (int i = 0; i < 8; i++) {
            int idx = i * 256 + tid;
            int si = idx >> 5, e = idx & 31;
            As[e][si] = g_x[(s0 + si) * EMBD + k0 + e];
            Bs[e][si] = W[(j0 + si) * EMBD + k0 + e];
        }
        __syncthreads();
#pragma unroll
        for (int e = 0; e < 32; e++) {
            float a[4], bb[4];
#pragma unroll
            for (int i = 0; i < 4; i++) { a[i] = As[e][ty * 4 + i]; bb[i] = Bs[e][tx * 4 + i]; }
#pragma unroll
            for (int i = 0; i < 4; i++)
#pragma unroll
                for (int j = 0; j < 4; j++) acc[i][j] = fmaf(a[i], bb[j], acc[i][j]);
        }
        __syncthreads();
    }
#pragma unroll
    for (int i = 0; i < 4; i++)
#pragma unroll
        for (int j = 0; j < 4; j++) {
            int jj = j0 + tx * 4 + j;
            g_xw[d][(s0 + ty * 4 + i) * NG + jj] = acc[i][j] + b1[jj] + b2[jj];
        }
}

// ---------------- kernel 3a: LSTM, 16-CTA cluster per direction (preferred) ----------------
// Same st.async protocol as R10. Each CTA owns 16 h-indices (64 Whh rows).
// Thread task: (row rr = tid>>2, quarter q = tid&3); 64 cols per task.
// Reduce across quarters with 2 shfls; gate warp = tid<16; fan-out 16 st.async.
// expect_tx per phase = 16 CTAs * 16 floats * 4 B = 1024 B.
__global__ void __cluster_dims__(CL16, 1, 1) __launch_bounds__(256, 1)
lstm_k16(const float* __restrict__ Whhf, const float* __restrict__ Whhb) {
    int dir = blockIdx.y;
    const float* Whh = dir ? Whhb : Whhf;
    const float* xw  = g_xw[dir];
    int r   = blockIdx.x;           // cluster rank 0..15
    int tid = threadIdx.x;
    int rr  = tid >> 2;             // 0..63 local row
    int q   = tid & 3;              // column quarter (64 cols)
    int gate = rr >> 4;
    int j4   = rr & 15;
    int gidx = r * 16 + j4;         // global h index
    int grow = gate * HDIRD + gidx; // Whh row / xw column

    // weights: 64 cols = 16 ulonglong2
    ulonglong2 Wp[16];
    const ulonglong2* wsrc =
        (const ulonglong2*)(Whh + (size_t)grow * HDIRD + q * 64);
#pragma unroll
    for (int k = 0; k < 16; k++) Wp[k] = wsrc[k];

    __shared__ __align__(16) float hbuf[2 * HBSTR];
    __shared__ float zbuf[64];
    __shared__ __align__(8) unsigned long long mbs[2];

    for (int i = tid; i < 2 * HBSTR; i += 256) hbuf[i] = 0.0f;
    uint32_t mbb = smem_u32(mbs);
    if (tid == 0) {
        mbar_init(mbb + 0, 1);
        mbar_init(mbb + 8, 1);
    }
    __syncthreads();
    CLUSTER_SYNC_();

    // hoisted remote addresses (used by tid<16)
    uint32_t hb0 = smem_u32(hbuf);
    uint32_t hoff4 = (uint32_t)(r * 16 + (tid & 15) + ((r >= 8) ? 4 : 0)) * 4u;
    uint32_t rh[CL16], rmb[CL16];
#pragma unroll
    for (int rk = 0; rk < CL16; rk++) {
        rh[rk]  = mapa_u32(hb0, rk) + hoff4;
        rmb[rk] = mapa_u32(mbb, rk);
    }

    float c = 0.0f;
    float xwreg = 0.0f;
    int pos0 = dir ? (SQ - 1) : 0;
    if (q == 0) xwreg = xw[(size_t)pos0 * NG + grow];

    for (int t = 0; t < SQ; t++) {
        int p = t & 1;
        int tn = t + 1;

        if (tid == 0 && tn < SQ)
            mbar_expect_tx(mbb + (uint32_t)((p ^ 1) * 8), 1024u);
        if (t) mbar_wait(mbb + (uint32_t)(p * 8), (uint32_t)(((t - 1) >> 1) & 1));
        __syncthreads();

        // quarter q covers cols [64q, 64q+64): half = q>>1, in-half offset (q&1)*64
        const ulonglong2* h2 =
            (const ulonglong2*)(hbuf + p * HBSTR + (q >> 1) * HPAD + (q & 1) * 64);
        unsigned long long a0 = 0ull, a1 = 0ull;
#pragma unroll
        for (int k = 0; k < 16; k++) {
            ulonglong2 hv = h2[k];
            fma2(a0, Wp[k].x, hv.x);
            fma2(a1, Wp[k].y, hv.y);
        }
        float2 f0 = *(float2*)&a0;
        float2 f1 = *(float2*)&a1;
        float acc = (f0.x + f0.y) + (f1.x + f1.y);
        acc += __shfl_xor_sync(0xffffffffu, acc, 1);   // quarters 0<->1, 2<->3
        acc += __shfl_xor_sync(0xffffffffu, acc, 2);   // pairs
        if (q == 0) zbuf[rr] = acc + xwreg;

        if (q == 0 && tn < SQ) {
            int pos = dir ? (SQ - 1 - tn) : tn;
            xwreg = xw[(size_t)pos * NG + grow];
        }
        __syncthreads();   // zbuf ready

        if (tid < 16) {
            float zi = zbuf[tid], zf = zbuf[16 + tid];
            float zg = zbuf[32 + tid], zo = zbuf[48 + tid];
            float ig = sigm_f(zi);
            float fg = sigm_f(zf);
            float gg = tanh_f(zg);
            float og = sigm_f(zo);
            c = fmaf(fg, c, ig * gg);
            float hn = og * tanh_f(c);

            int pos = dir ? (SQ - 1 - t) : t;
            g_h[dir][(size_t)pos * HDIRD + r * 16 + tid] = hn;

            if (tn < SQ) {
                uint32_t bo  = (uint32_t)((p ^ 1) * HBSTR * 4);
                uint32_t mbo = (uint32_t)((p ^ 1) * 8);
#pragma unroll
                for (int rk = 0; rk < CL16; rk++)
                    st_async_f32(rh[rk] + bo, hn, rmb[rk] + mbo);
            }
        }
    }
    CLUSTER_SYNC_();
}

// ---------------- kernel 3b: LSTM, 8-CTA cluster (R10-proven fallback) ----------------
__global__ void __cluster_dims__(CL, 1, 1) __launch_bounds__(256, 1)
lstm_k8(const float* __restrict__ Whhf, const float* __restrict__ Whhb) {
    int dir = blockIdx.y;
    const float* Whh = dir ? Whhb : Whhf;
    const float* xw  = g_xw[dir];
    int r   = blockIdx.x;
    int tid = threadIdx.x;
    int rr   = tid >> 1;
    int half = tid & 1;
    int gate = rr >> 5;
    int j5   = rr & 31;
    int grow = gate * HDIRD + r * 32 + j5;

    ulonglong2 Wp[32];
    const ulonglong2* wsrc =
        (const ulonglong2*)(Whh + (size_t)grow * HDIRD + half * 128);
#pragma unroll
    for (int k = 0; k < 32; k++) Wp[k] = wsrc[k];

    __shared__ __align__(16) float hbuf[2 * HBSTR];
    __shared__ float zbuf[128];
    __shared__ __align__(8) unsigned long long mbs[2];

    for (int i = tid; i < 2 * HBSTR; i += 256) hbuf[i] = 0.0f;
    uint32_t mbb = smem_u32(mbs);
    if (tid == 0) {
        mbar_init(mbb + 0, 1);
        mbar_init(mbb + 8, 1);
    }
    __syncthreads();
    CLUSTER_SYNC_();

    uint32_t hb0 = smem_u32(hbuf);
    uint32_t hoff4 = (uint32_t)(r * 32 + (tid & 31) + ((r >= 4) ? 4 : 0)) * 4u;
    uint32_t rh[CL], rmb[CL];
#pragma unroll
    for (int rk = 0; rk < CL; rk++) {
        rh[rk]  = mapa_u32(hb0, rk) + hoff4;
        rmb[rk] = mapa_u32(mbb, rk);
    }

    float c = 0.0f;
    float xwreg = 0.0f;
    int pos0 = dir ? (SQ - 1) : 0;
    if (!half) xwreg = xw[(size_t)pos0 * NG + grow];

    for (int t = 0; t < SQ; t++) {
        int p = t & 1;
        int tn = t + 1;

        if (tid == 0 && tn < SQ)
            mbar_expect_tx(mbb + (uint32_t)((p ^ 1) * 8), 1024u);
        if (t) mbar_wait(mbb + (uint32_t)(p * 8), (uint32_t)(((t - 1) >> 1) & 1));
        __syncthreads();

        const ulonglong2* h2 =
            (const ulonglong2*)(hbuf + p * HBSTR + half * HPAD);
        unsigned long long a0 = 0ull, a1 = 0ull;
#pragma unroll
        for (int k = 0; k < 32; k++) {
            ulonglong2 hv = h2[k];
            fma2(a0, Wp[k].x, hv.x);
            fma2(a1, Wp[k].y, hv.y);
        }
        float2 f0 = *(float2*)&a0;
        float2 f1 = *(float2*)&a1;
        float acc = (f0.x + f0.y) + (f1.x + f1.y);
        acc += __shfl_xor_sync(0xffffffffu, acc, 1);
        if (!half) zbuf[rr] = acc + xwreg;

        if (!half && tn < SQ) {
            int pos = dir ? (SQ - 1 - tn) : tn;
            xwreg = xw[(size_t)pos * NG + grow];
        }
        __syncthreads();

        if (tid < 32) {
            float zi = zbuf[tid], zf = zbuf[32 + tid];
            float zg = zbuf[64 + tid], zo = zbuf[96 + tid];
            float ig = sigm_f(zi);
            float fg = sigm_f(zf);
            float gg = tanh_f(zg);
            float og = sigm_f(zo);
            c = fmaf(fg, c, ig * gg);
            float hn = og * tanh_f(c);

            int pos = dir ? (SQ - 1 - t) : t;
            g_h[dir][(size_t)pos * HDIRD + r * 32 + tid] = hn;

            if (tn < SQ) {
                uint32_t bo  = (uint32_t)((p ^ 1) * HBSTR * 4);
                uint32_t mbo = (uint32_t)((p ^ 1) * 8);
#pragma unroll
                for (int rk = 0; rk < CL; rk++)
                    st_async_f32(rh[rk] + bo, hn, rmb[rk] + mbo);
            }
        }
    }
    CLUSTER_SYNC_();
}

// ---------------- kernel 4: feats = [h_f | h_b] @ Wout^T + b (warp per s) ----------------
__global__ void feats_k(const float* __restrict__ Wout, const float* __restrict__ bout) {
    __shared__ float Wsm[TAGS][512];
    __shared__ float bsm[TAGS];
    int tid = threadIdx.x;
    for (int i = tid; i < TAGS * 512; i += 256) Wsm[i / 512][i % 512] = Wout[i];
    if (tid < TAGS) bsm[tid] = bout[tid];
    __syncthreads();

    int lane = tid & 31;
    int s = blockIdx.x * 8 + (tid >> 5);     // warp per sequence position
    float acc[TAGS];
#pragma unroll
    for (int t = 0; t < TAGS; t++) acc[t] = 0.0f;

#pragma unroll
    for (int d = 0; d < 2; d++) {
        const float* hrow = (d == 0) ? &g_h[0][(size_t)s * HDIRD]
                                     : &g_h[1][(size_t)s * HDIRD];
#pragma unroll
        for (int k0 = 0; k0 < HDIRD; k0 += 32) {
            float x = hrow[k0 + lane];
#pragma unroll
            for (int t = 0; t < TAGS; t++)
                acc[t] = fmaf(x, Wsm[t][d * 256 + k0 + lane], acc[t]);
        }
    }
#pragma unroll
    for (int t = 0; t < TAGS; t++) {
#pragma unroll
        for (int o = 16; o > 0; o >>= 1) acc[t] += __shfl_xor_sync(0xffffffffu, acc[t], o);
    }
    if (lane == 0) {
#pragma unroll
        for (int t = 0; t < TAGS; t++) g_feats[s * TAGS + t] = acc[t] + bsm[t];
    }
}

// ---------------- kernel 5: Viterbi decode (single warp) ----------------
__global__ void viterbi_k(const float* __restrict__ trans, float* __restrict__ out,
                          int out_size) {
    __shared__ unsigned char bp[SQ][TAGS];   // 40 KB backpointers
    int n = threadIdx.x;

    float tr[TAGS];
#pragma unroll
    for (int p = 0; p < TAGS; p++) tr[p] = (n < TAGS) ? trans[n * TAGS + p] : NEGV;

    float fvr = (n == 8) ? 0.0f : NEGV;      // START = 8
    float fa = (n < TAGS) ? g_feats[0 * TAGS + n] : 0.0f;
    float fb = (n < TAGS) ? g_feats[1 * TAGS + n] : 0.0f;

    for (int t = 0; t < SQ; t++) {
        float m = -3.4e38f;
        int bi = 0;
#pragma unroll
        for (int p = 0; p < TAGS; p++) {
            float v = __shfl_sync(0xffffffffu, fvr, p) + tr[p];
            if (v > m) { m = v; bi = p; }    // strict > keeps first max (jnp.argmax)
        }
        if (n < TAGS) bp[t][n] = (unsigned char)bi;
        float nf = m + fa;
        fa = fb;
        int tn = t + 2;
        if (n < TAGS && tn < SQ) fb = g_feats[tn * TAGS + n];
        fvr = nf;
    }

    float term = fvr + ((n < TAGS) ? trans[9 * TAGS + n] : NEGV);
    float bm = -3.4e38f;
    int bidx = 0;
#pragma unroll
    for (int p = 0; p < TAGS; p++) {
        float v = __shfl_sync(0xffffffffu, term, p);
        if (v > bm) { bm = v; bidx = p; }
    }
    if (n == 0) {
        int off = (out_size > SQ) ? 1 : 0;
        if (off) out[0] = bm;                // score first, then path
        int tag = bidx;
        for (int t = SQ - 1; t >= 0; t--) {
            out[off + t] = (float)tag;
            tag = bp[t][tag];
        }
    }
}

// ---------------- launch ----------------
extern "C" void kernel_launch(void* const* d_in, const int* in_sizes, int n_in,
                              void* d_out, int out_size) {
    const int*   sent  = (const int*)d_in[0];
    const float* emb   = (const float*)d_in[1];
    const float* Wih_f = (const float*)d_in[2];
    const float* Whh_f = (const float*)d_in[3];
    const float* bih_f = (const float*)d_in[4];
    const float* bhh_f = (const float*)d_in[5];
    const float* Wih_b = (const float*)d_in[6];
    const float* Whh_b = (const float*)d_in[7];
    const float* bih_b = (const float*)d_in[8];
    const float* bhh_b = (const float*)d_in[9];
    const float* W_out = (const float*)d_in[10];
    const float* b_out = (const float*)d_in[11];
    const float* trans = (const float*)d_in[12];
    float* out = (float*)d_out;

    gather_k<<<(SQ * 64) / 256, 256>>>(sent, emb);
    xw_gemm_k<<<dim3(SQ / 64, NG / 64, 2), 256>>>(Wih_f, Wih_b, bih_f, bhh_f, bih_b, bhh_b);

    // prefer 16-CTA clusters; deterministic fallback to proven 8-CTA version
    cudaError_t e = cudaFuncSetAttribute(
        lstm_k16, cudaFuncAttributeNonPortableClusterSizeAllowed, 1);
    if (e == cudaSuccess) {
        lstm_k16<<<dim3(CL16, 2, 1), 256>>>(Whh_f, Whh_b);
    } else {
        lstm_k8<<<dim3(CL, 2, 1), 256>>>(Whh_f, Whh_b);
    }

    feats_k<<<SQ / 8, 256>>>(W_out, b_out);   // 512 blocks x 8 warps = 4096 positions
    viterbi_k<<<1, 32>>>(trans, out, out_size);
}

// round 12
// speedup vs baseline: 1.0590x; 1.0590x over previous
#include <cuda_runtime.h>
#include <cstdint>

// ---------------- problem constants ----------------
#define SQ    4096          // sequence length
#define EMBD  256
#define HDIRD 256           // HID/2
#define NG    1024          // 4*HDIR
#define TAGS  10
#define NEGV  -10000.0f
#define CL    8             // cluster size per direction
#define HPAD  132           // padded half stride in floats (128+4 -> halves in different banks)
#define HBSTR 264           // one buffer = 2 halves = 264 floats

// ---------------- scratch (device globals; no dynamic alloc) ----------------
__device__ float g_x[SQ * EMBD];              // gathered embeddings   4 MB
__device__ float g_xw[2][SQ * NG];            // input-gate precompute 32 MB
__device__ float g_h[2][SQ * HDIRD];          // hidden states         8 MB
__device__ float g_feats[SQ * TAGS];          // CRF emission feats

// ---------------- helpers ----------------
__device__ __forceinline__ uint32_t smem_u32(const void* p) {
    return (uint32_t)__cvta_generic_to_shared(p);
}
__device__ __forceinline__ uint32_t mapa_u32(uint32_t laddr, uint32_t rank) {
    uint32_t rem;
    asm("mapa.shared::cluster.u32 %0, %1, %2;" : "=r"(rem) : "r"(laddr), "r"(rank));
    return rem;
}
// bulk DSMEM copy: local smem -> peer smem, complete_tx at the peer's mbarrier
__device__ __forceinline__ void bulk_copy_dsmem(uint32_t dst, uint32_t src,
                                                uint32_t bytes, uint32_t rmbar) {
    asm volatile(
        "cp.async.bulk.shared::cluster.shared::cta.mbarrier::complete_tx::bytes "
        "[%0], [%1], %2, [%3];"
        :: "r"(dst), "r"(src), "r"(bytes), "r"(rmbar) : "memory");
}
__device__ __forceinline__ void fence_proxy_async_cta() {
    asm volatile("fence.proxy.async.shared::cta;" ::: "memory");
}
__device__ __forceinline__ void mbar_init(uint32_t a, uint32_t cnt) {
    asm volatile("mbarrier.init.shared.b64 [%0], %1;" :: "r"(a), "r"(cnt) : "memory");
}
__device__ __forceinline__ void mbar_expect_tx(uint32_t a, uint32_t bytes) {
    asm volatile("mbarrier.arrive.expect_tx.shared.b64 _, [%0], %1;"
                 :: "r"(a), "r"(bytes) : "memory");
}
// exact known-good wait form from ptx_helpers.cuh (local CTA scope)
__device__ __forceinline__ void mbar_wait(uint32_t a, uint32_t par) {
    uint32_t done;
    asm volatile(
        "{\n\t.reg .pred p;\n\t"
        "mbarrier.try_wait.parity.acquire.cta.shared::cta.b64 p, [%1], %2;\n\t"
        "selp.b32 %0, 1, 0, p;\n\t}"
        : "=r"(done) : "r"(a), "r"(par) : "memory");
    if (!done) {
        asm volatile(
            "{\n\t.reg .pred P1;\n\t"
            "WAIT_LOOP_%=:\n\t"
            "mbarrier.try_wait.parity.acquire.cta.shared::cta.b64 P1, [%0], %1, 0x989680;\n\t"
            "@P1 bra.uni WAIT_DONE_%=;\n\t"
            "bra.uni WAIT_LOOP_%=;\n\t"
            "WAIT_DONE_%=:\n\t}"
            :: "r"(a), "r"(par) : "memory");
    }
}
#define CLUSTER_SYNC_() do {                                                   \
    asm volatile("barrier.cluster.arrive.aligned;" ::: "memory");              \
    asm volatile("barrier.cluster.wait.aligned;"   ::: "memory");              \
} while (0)

__device__ __forceinline__ void fma2(unsigned long long& d,
                                     unsigned long long a, unsigned long long b) {
    asm("fma.rn.f32x2 %0, %1, %2, %0;" : "+l"(d) : "l"(a), "l"(b));
}

__device__ __forceinline__ float sigm_f(float x) {
    return 1.0f / (1.0f + __expf(-x));
}
__device__ __forceinline__ float tanh_f(float x) {
    float e = __expf(-2.0f * fabsf(x));
    float r = (1.0f - e) / (1.0f + e);
    return copysignf(r, x);
}

// ---------------- kernel 1: embedding gather ----------------
__global__ void gather_k(const int* __restrict__ sent, const float* __restrict__ emb) {
    int gid = blockIdx.x * blockDim.x + threadIdx.x;  // over SQ*64 float4
    int row = gid >> 6;
    int c   = gid & 63;
    ((float4*)g_x)[row * 64 + c] =
        ((const float4*)emb)[(size_t)sent[row] * 64 + c];
}

// ---------------- kernel 2: xw = x @ Wih^T + (bih+bhh), both directions ----------------
__global__ void xw_gemm_k(const float* __restrict__ Wf, const float* __restrict__ Wb,
                          const float* __restrict__ bihf, const float* __restrict__ bhhf,
                          const float* __restrict__ bihb, const float* __restrict__ bhhb) {
    int d = blockIdx.z;
    const float* W  = d ? Wb : Wf;
    const float* b1 = d ? bihb : bihf;
    const float* b2 = d ? bhhb : bhhf;

    __shared__ float As[32][65];
    __shared__ float Bs[32][65];

    int s0 = blockIdx.x * 64;
    int j0 = blockIdx.y * 64;
    int tid = threadIdx.x;
    int tx = tid & 15, ty = tid >> 4;

    float acc[4][4];
#pragma unroll
    for (int i = 0; i < 4; i++)
#pragma unroll
        for (int j = 0; j < 4; j++) acc[i][j] = 0.0f;

    for (int k0 = 0; k0 < EMBD; k0 += 32) {
#pragma unroll
        for (int i = 0; i < 8; i++) {
            int idx = i * 256 + tid;
            int si = idx >> 5, e = idx & 31;
            As[e][si] = g_x[(s0 + si) * EMBD + k0 + e];
            Bs[e][si] = W[(j0 + si) * EMBD + k0 + e];
        }
        __syncthreads();
#pragma unroll
        for (int e = 0; e < 32; e++) {
            float a[4], bb[4];
#pragma unroll
            for (int i = 0; i < 4; i++) { a[i] = As[e][ty * 4 + i]; bb[i] = Bs[e][tx * 4 + i]; }
#pragma unroll
            for (int i = 0; i < 4; i++)
#pragma unroll
                for (int j = 0; j < 4; j++) acc[i][j] = fmaf(a[i], bb[j], acc[i][j]);
        }
        __syncthreads();
    }
#pragma unroll
    for (int i = 0; i < 4; i++)
#pragma unroll
        for (int j = 0; j < 4; j++) {
            int jj = j0 + tx * 4 + j;
            g_xw[d][(s0 + ty * 4 + i) * NG + jj] = acc[i][j] + b1[jj] + b2[jj];
        }
}

// ---------------- kernel 3: recurrent LSTM, one 8-CTA cluster per direction ----------------
// R10 protocol (st.async-style completion, local acquire waits), transport
// switched to 8x 128-byte bulk DSMEM copies:
//   gate warp stages its 32 h's in stg[b] (STS), __syncwarp, lane 0 issues
//   fence.proxy.async then one cp.async.bulk per rank with complete_tx at the
//   destination's mbar[b]. expect_tx per phase = 8 x 128 B = 1024 B.
// Staging reuse hazard: peer's next-step arrival implies this step's source
// read completed (its wait needed our delivery), so parity double-buffer is safe.
__global__ void __cluster_dims__(CL, 1, 1) __launch_bounds__(256, 1)
lstm_k(const float* __restrict__ Whhf, const float* __restrict__ Whhb) {
    int dir = blockIdx.y;
    const float* Whh = dir ? Whhb : Whhf;
    const float* xw  = g_xw[dir];
    int r   = blockIdx.x;           // cluster rank
    int tid = threadIdx.x;
    int rr   = tid >> 1;            // 0..127 local row
    int half = tid & 1;             // column half
    int gate = rr >> 5;
    int j5   = rr & 31;
    int grow = gate * HDIRD + r * 32 + j5;   // global Whh row / xw column

    // weights -> registers, packed as f32 pairs (half row = 128 cols)
    ulonglong2 Wp[32];
    const ulonglong2* wsrc =
        (const ulonglong2*)(Whh + (size_t)grow * HDIRD + half * 128);
#pragma unroll
    for (int k = 0; k < 32; k++) Wp[k] = wsrc[k];

    __shared__ __align__(16) float hbuf[2 * HBSTR];   // halves padded by 16B
    __shared__ __align__(16) float stg[2][32];        // outgoing h staging (parity)
    __shared__ float zbuf[128];
    __shared__ __align__(8) unsigned long long mbs[2]; // mbar per buffer

    for (int i = tid; i < 2 * HBSTR; i += 256) hbuf[i] = 0.0f;
    uint32_t mbb = smem_u32(mbs);
    if (tid == 0) {
        mbar_init(mbb + 0, 1);
        mbar_init(mbb + 8, 1);
    }
    __syncthreads();
    CLUSTER_SYNC_();   // zeroed hbuf + initialized mbarriers visible cluster-wide

    // hoisted remote addresses:
    //   rdst[rk] = rank rk's hbuf slot for THIS CTA's 128-byte chunk
    //   rmb[rk]  = rank rk's mbarrier base
    uint32_t hb0 = smem_u32(hbuf);
    uint32_t sg0 = smem_u32(&stg[0][0]);
    uint32_t chunk_off = (uint32_t)(r * 32 + ((r >= 4) ? 4 : 0)) * 4u;  // 16B-aligned
    uint32_t rdst[CL], rmb[CL];
#pragma unroll
    for (int rk = 0; rk < CL; rk++) {
        rdst[rk] = mapa_u32(hb0, rk) + chunk_off;
        rmb[rk]  = mapa_u32(mbb, rk);
    }

    float c = 0.0f;
    float xwreg = 0.0f;
    int pos0 = dir ? (SQ - 1) : 0;
    if (!half) xwreg = xw[(size_t)pos0 * NG + grow];

    for (int t = 0; t < SQ; t++) {
        int p = t & 1;
        int tn = t + 1;

        // post this phase's expectation for the buffer being filled (p^1)
        if (tid == 0 && tn < SQ)
            mbar_expect_tx(mbb + (uint32_t)((p ^ 1) * 8), 1024u);
        // wait for buffer p to be complete (skip first step: zero-initialized)
        if (t) mbar_wait(mbb + (uint32_t)(p * 8), (uint32_t)(((t - 1) >> 1) & 1));
        __syncthreads();   // all warps see completed buffer; zbuf safe to rewrite

        const ulonglong2* h2 =
            (const ulonglong2*)(hbuf + p * HBSTR + half * HPAD);
        unsigned long long a0 = 0ull, a1 = 0ull;
#pragma unroll
        for (int k = 0; k < 32; k++) {
            ulonglong2 hv = h2[k];
            fma2(a0, Wp[k].x, hv.x);
            fma2(a1, Wp[k].y, hv.y);
        }
        float2 f0 = *(float2*)&a0;
        float2 f1 = *(float2*)&a1;
        float acc = (f0.x + f0.y) + (f1.x + f1.y);
        acc += __shfl_xor_sync(0xffffffffu, acc, 1);   // combine column halves
        if (!half) zbuf[rr] = acc + xwreg;

        // prefetch next step's xw
        if (!half && tn < SQ) {
            int pos = dir ? (SQ - 1 - tn) : tn;
            xwreg = xw[(size_t)pos * NG + grow];
        }
        __syncthreads();   // zbuf ready

        if (tid < 32) {
            float zi = zbuf[tid], zf = zbuf[32 + tid];
            float zg = zbuf[64 + tid], zo = zbuf[96 + tid];
            float ig = sigm_f(zi);
            float fg = sigm_f(zf);
            float gg = tanh_f(zg);
            float og = sigm_f(zo);
            c = fmaf(fg, c, ig * gg);
            float hn = og * tanh_f(c);

            int pos = dir ? (SQ - 1 - t) : t;
            g_h[dir][(size_t)pos * HDIRD + r * 32 + tid] = hn;

            if (tn < SQ) {
                int b = p ^ 1;
                stg[b][tid] = hn;          // stage outgoing chunk (contiguous 128 B)
                __syncwarp();
                if (tid == 0) {
                    fence_proxy_async_cta();   // generic STS -> async-proxy reads
                    uint32_t src = sg0 + (uint32_t)(b * 128);
                    uint32_t bo  = (uint32_t)(b * HBSTR * 4);
                    uint32_t mbo = (uint32_t)(b * 8);
#pragma unroll
                    for (int rk = 0; rk < CL; rk++)
                        bulk_copy_dsmem(rdst[rk] + bo, src, 128u, rmb[rk] + mbo);
                }
            }
        }
        // NO cluster.sync: next iteration's mbar_wait provides ordering.
    }
    CLUSTER_SYNC_();   // keep SMEM alive until all peers are done
}

// ---------------- kernel 4: feats = [h_f | h_b] @ Wout^T + b (warp per s) ----------------
__global__ void feats_k(const float* __restrict__ Wout, const float* __restrict__ bout) {
    __shared__ float Wsm[TAGS][512];
    __shared__ float bsm[TAGS];
    int tid = threadIdx.x;
    for (int i = tid; i < TAGS * 512; i += 256) Wsm[i / 512][i % 512] = Wout[i];
    if (tid < TAGS) bsm[tid] = bout[tid];
    __syncthreads();

    int lane = tid & 31;
    int s = blockIdx.x * 8 + (tid >> 5);     // warp per sequence position
    float acc[TAGS];
#pragma unroll
    for (int t = 0; t < TAGS; t++) acc[t] = 0.0f;

#pragma unroll
    for (int d = 0; d < 2; d++) {
        const float* hrow = (d == 0) ? &g_h[0][(size_t)s * HDIRD]
                                     : &g_h[1][(size_t)s * HDIRD];
#pragma unroll
        for (int k0 = 0; k0 < HDIRD; k0 += 32) {
            float x = hrow[k0 + lane];
#pragma unroll
            for (int t = 0; t < TAGS; t++)
                acc[t] = fmaf(x, Wsm[t][d * 256 + k0 + lane], acc[t]);
        }
    }
#pragma unroll
    for (int t = 0; t < TAGS; t++) {
#pragma unroll
        for (int o = 16; o > 0; o >>= 1) acc[t] += __shfl_xor_sync(0xffffffffu, acc[t], o);
    }
    if (lane == 0) {
#pragma unroll
        for (int t = 0; t < TAGS; t++) g_feats[s * TAGS + t] = acc[t] + bsm[t];
    }
}

// ---------------- kernel 5: Viterbi decode (single warp) ----------------
__global__ void viterbi_k(const float* __restrict__ trans, float* __restrict__ out,
                          int out_size) {
    __shared__ unsigned char bp[SQ][TAGS];   // 40 KB backpointers
    int n = threadIdx.x;

    float tr[TAGS];
#pragma unroll
    for (int p = 0; p < TAGS; p++) tr[p] = (n < TAGS) ? trans[n * TAGS + p] : NEGV;

    float fvr = (n == 8) ? 0.0f : NEGV;      // START = 8
    float fa = (n < TAGS) ? g_feats[0 * TAGS + n] : 0.0f;
    float fb = (n < TAGS) ? g_feats[1 * TAGS + n] : 0.0f;

    for (int t = 0; t < SQ; t++) {
        float m = -3.4e38f;
        int bi = 0;
#pragma unroll
        for (int p = 0; p < TAGS; p++) {
            float v = __shfl_sync(0xffffffffu, fvr, p) + tr[p];
            if (v > m) { m = v; bi = p; }    // strict > keeps first max (jnp.argmax)
        }
        if (n < TAGS) bp[t][n] = (unsigned char)bi;
        float nf = m + fa;
        fa = fb;
        int tn = t + 2;
        if (n < TAGS && tn < SQ) fb = g_feats[tn * TAGS + n];
        fvr = nf;
    }

    float term = fvr + ((n < TAGS) ? trans[9 * TAGS + n] : NEGV);
    float bm = -3.4e38f;
    int bidx = 0;
#pragma unroll
    for (int p = 0; p < TAGS; p++) {
        float v = __shfl_sync(0xffffffffu, term, p);
        if (v > bm) { bm = v; bidx = p; }
    }
    if (n == 0) {
        int off = (out_size > SQ) ? 1 : 0;
        if (off) out[0] = bm;                // score first, then path
        int tag = bidx;
        for (int t = SQ - 1; t >= 0; t--) {
            out[off + t] = (float)tag;
            tag = bp[t][tag];
        }
    }
}

// ---------------- launch ----------------
extern "C" void kernel_launch(void* const* d_in, const int* in_sizes, int n_in,
                              void* d_out, int out_size) {
    const int*   sent  = (const int*)d_in[0];
    const float* emb   = (const float*)d_in[1];
    const float* Wih_f = (const float*)d_in[2];
    const float* Whh_f = (const float*)d_in[3];
    const float* bih_f = (const float*)d_in[4];
    const float* bhh_f = (const float*)d_in[5];
    const float* Wih_b = (const float*)d_in[6];
    const float* Whh_b = (const float*)d_in[7];
    const float* bih_b = (const float*)d_in[8];
    const float* bhh_b = (const float*)d_in[9];
    const float* W_out = (const float*)d_in[10];
    const float* b_out = (const float*)d_in[11];
    const float* trans = (const float*)d_in[12];
    float* out = (float*)d_out;

    gather_k<<<(SQ * 64) / 256, 256>>>(sent, emb);
    xw_gemm_k<<<dim3(SQ / 64, NG / 64, 2), 256>>>(Wih_f, Wih_b, bih_f, bhh_f, bih_b, bhh_b);
    lstm_k<<<dim3(CL, 2, 1), 256>>>(Whh_f, Whh_b);
    feats_k<<<SQ / 8, 256>>>(W_out, b_out);   // 512 blocks x 8 warps = 4096 positions
    viterbi_k<<<1, 32>>>(trans, out, out_size);
}

// round 13
// speedup vs baseline: 1.2642x; 1.1938x over previous
#include <cuda_runtime.h>
#include <cstdint>

// ---------------- problem constants ----------------
#define SQ    4096          // sequence length
#define EMBD  256
#define HDIRD 256           // HID/2
#define NG    1024          // 4*HDIR
#define TAGS  10
#define NEGV  -10000.0f
#define CL    8             // cluster size per direction
#define HPAD  132           // padded half stride in floats (128+4 -> halves in different banks)
#define HBSTR 264           // one buffer = 2 halves = 264 floats

// ---------------- scratch (device globals; no dynamic alloc) ----------------
__device__ float g_x[SQ * EMBD];              // gathered embeddings   4 MB
__device__ float g_xw[2][SQ * NG];            // input-gate precompute 32 MB
__device__ float g_h[2][SQ * HDIRD];          // hidden states         8 MB
__device__ float g_feats[SQ * TAGS];          // CRF emission feats

// ---------------- helpers ----------------
__device__ __forceinline__ uint32_t smem_u32(const void* p) {
    return (uint32_t)__cvta_generic_to_shared(p);
}
__device__ __forceinline__ uint32_t mapa_u32(uint32_t laddr, uint32_t rank) {
    uint32_t rem;
    asm("mapa.shared::cluster.u32 %0, %1, %2;" : "=r"(rem) : "r"(laddr), "r"(rank));
    return rem;
}
// 8-byte remote store with completion tx delivered to the DESTINATION CTA's mbarrier
__device__ __forceinline__ void st_async_b64(uint32_t raddr, unsigned long long v,
                                             uint32_t rmbar) {
    asm volatile(
        "st.async.shared::cluster.mbarrier::complete_tx::bytes.b64 [%0], %1, [%2];"
        :: "r"(raddr), "l"(v), "r"(rmbar) : "memory");
}
__device__ __forceinline__ void mbar_init(uint32_t a, uint32_t cnt) {
    asm volatile("mbarrier.init.shared.b64 [%0], %1;" :: "r"(a), "r"(cnt) : "memory");
}
__device__ __forceinline__ void mbar_expect_tx(uint32_t a, uint32_t bytes) {
    asm volatile("mbarrier.arrive.expect_tx.shared.b64 _, [%0], %1;"
                 :: "r"(a), "r"(bytes) : "memory");
}
// exact known-good wait form from ptx_helpers.cuh (local CTA scope)
__device__ __forceinline__ void mbar_wait(uint32_t a, uint32_t par) {
    uint32_t done;
    asm volatile(
        "{\n\t.reg .pred p;\n\t"
        "mbarrier.try_wait.parity.acquire.cta.shared::cta.b64 p, [%1], %2;\n\t"
        "selp.b32 %0, 1, 0, p;\n\t}"
        : "=r"(done) : "r"(a), "r"(par) : "memory");
    if (!done) {
        asm volatile(
            "{\n\t.reg .pred P1;\n\t"
            "WAIT_LOOP_%=:\n\t"
            "mbarrier.try_wait.parity.acquire.cta.shared::cta.b64 P1, [%0], %1, 0x989680;\n\t"
            "@P1 bra.uni WAIT_DONE_%=;\n\t"
            "bra.uni WAIT_LOOP_%=;\n\t"
            "WAIT_DONE_%=:\n\t}"
            :: "r"(a), "r"(par) : "memory");
    }
}
#define CLUSTER_SYNC_() do {                                                   \
    asm volatile("barrier.cluster.arrive.aligned;" ::: "memory");              \
    asm volatile("barrier.cluster.wait.aligned;"   ::: "memory");              \
} while (0)

__device__ __forceinline__ void fma2(unsigned long long& d,
                                     unsigned long long a, unsigned long long b) {
    asm("fma.rn.f32x2 %0, %1, %2, %0;" : "+l"(d) : "l"(a), "l"(b));
}

__device__ __forceinline__ float sigm_f(float x) {
    return 1.0f / (1.0f + __expf(-x));
}
__device__ __forceinline__ float tanh_f(float x) {
    float e = __expf(-2.0f * fabsf(x));
    float r = (1.0f - e) / (1.0f + e);
    return copysignf(r, x);
}

// ---------------- kernel 1: embedding gather ----------------
__global__ void gather_k(const int* __restrict__ sent, const float* __restrict__ emb) {
    int gid = blockIdx.x * blockDim.x + threadIdx.x;  // over SQ*64 float4
    int row = gid >> 6;
    int c   = gid & 63;
    ((float4*)g_x)[row * 64 + c] =
        ((const float4*)emb)[(size_t)sent[row] * 64 + c];
}

// ---------------- kernel 2: xw = x @ Wih^T + (bih+bhh), both directions ----------------
__global__ void xw_gemm_k(const float* __restrict__ Wf, const float* __restrict__ Wb,
                          const float* __restrict__ bihf, const float* __restrict__ bhhf,
                          const float* __restrict__ bihb, const float* __restrict__ bhhb) {
    int d = blockIdx.z;
    const float* W  = d ? Wb : Wf;
    const float* b1 = d ? bihb : bihf;
    const float* b2 = d ? bhhb : bhhf;

    __shared__ float As[32][65];
    __shared__ float Bs[32][65];

    int s0 = blockIdx.x * 64;
    int j0 = blockIdx.y * 64;
    int tid = threadIdx.x;
    int tx = tid & 15, ty = tid >> 4;

    float acc[4][4];
#pragma unroll
    for (int i = 0; i < 4; i++)
#pragma unroll
        for (int j = 0; j < 4; j++) acc[i][j] = 0.0f;

    for (int k0 = 0; k0 < EMBD; k0 += 32) {
#pragma unroll
        for (int i = 0; i < 8; i++) {
            int idx = i * 256 + tid;
            int si = idx >> 5, e = idx & 31;
            As[e][si] = g_x[(s0 + si) * EMBD + k0 + e];
            Bs[e][si] = W[(j0 + si) * EMBD + k0 + e];
        }
        __syncthreads();
#pragma unroll
        for (int e = 0; e < 32; e++) {
            float a[4], bb[4];
#pragma unroll
            for (int i = 0; i < 4; i++) { a[i] = As[e][ty * 4 + i]; bb[i] = Bs[e][tx * 4 + i]; }
#pragma unroll
            for (int i = 0; i < 4; i++)
#pragma unroll
                for (int j = 0; j < 4; j++) acc[i][j] = fmaf(a[i], bb[j], acc[i][j]);
        }
        __syncthreads();
    }
#pragma unroll
    for (int i = 0; i < 4; i++)
#pragma unroll
        for (int j = 0; j < 4; j++) {
            int jj = j0 + tx * 4 + j;
            g_xw[d][(s0 + ty * 4 + i) * NG + jj] = acc[i][j] + b1[jj] + b2[jj];
        }
}

// ---------------- kernel 3: recurrent LSTM, one 8-CTA cluster per direction ----------------
// R10 protocol verbatim (expect_tx 1024 B/phase, local acquire waits, parity
// double buffer), with the fan-out pair-packed: even gate lanes send b64
// messages (own h in low word, odd partner's in high) -> 128 messages/step
// instead of 256; bytes identical. g_h global store moved after the sends.
__global__ void __cluster_dims__(CL, 1, 1) __launch_bounds__(256, 1)
lstm_k(const float* __restrict__ Whhf, const float* __restrict__ Whhb) {
    int dir = blockIdx.y;
    const float* Whh = dir ? Whhb : Whhf;
    const float* xw  = g_xw[dir];
    int r   = blockIdx.x;           // cluster rank
    int tid = threadIdx.x;
    int rr   = tid >> 1;            // 0..127 local row
    int half = tid & 1;             // column half
    int gate = rr >> 5;
    int j5   = rr & 31;
    int grow = gate * HDIRD + r * 32 + j5;   // global Whh row / xw column

    // weights -> registers, packed as f32 pairs (half row = 128 cols)
    ulonglong2 Wp[32];
    const ulonglong2* wsrc =
        (const ulonglong2*)(Whh + (size_t)grow * HDIRD + half * 128);
#pragma unroll
    for (int k = 0; k < 32; k++) Wp[k] = wsrc[k];

    __shared__ __align__(16) float hbuf[2 * HBSTR];   // halves padded by 16B
    __shared__ float zbuf[128];
    __shared__ __align__(8) unsigned long long mbs[2]; // mbar per buffer

    for (int i = tid; i < 2 * HBSTR; i += 256) hbuf[i] = 0.0f;
    uint32_t mbb = smem_u32(mbs);
    if (tid == 0) {
        mbar_init(mbb + 0, 1);
        mbar_init(mbb + 8, 1);
    }
    __syncthreads();
    CLUSTER_SYNC_();   // zeroed hbuf + initialized mbarriers visible cluster-wide

    // hoisted remote addresses (used by even lanes of warp 0):
    // slot for global h index (r*32 + tid): padded by +4 floats if in half1
    uint32_t hb0 = smem_u32(hbuf);
    uint32_t hoff4 = (uint32_t)(r * 32 + (tid & 31) + ((r >= 4) ? 4 : 0)) * 4u;
    uint32_t rh[CL], rmb[CL];
#pragma unroll
    for (int rk = 0; rk < CL; rk++) {
        rh[rk]  = mapa_u32(hb0, rk) + hoff4;   // 8B-aligned for even tid
        rmb[rk] = mapa_u32(mbb, rk);
    }

    float c = 0.0f;
    float xwreg = 0.0f;
    int pos0 = dir ? (SQ - 1) : 0;
    if (!half) xwreg = xw[(size_t)pos0 * NG + grow];

    for (int t = 0; t < SQ; t++) {
        int p = t & 1;
        int tn = t + 1;

        // post this phase's expectation for the buffer being filled (p^1)
        if (tid == 0 && tn < SQ)
            mbar_expect_tx(mbb + (uint32_t)((p ^ 1) * 8), 1024u);
        // wait for buffer p to be complete (skip first step: zero-initialized)
        if (t) mbar_wait(mbb + (uint32_t)(p * 8), (uint32_t)(((t - 1) >> 1) & 1));
        __syncthreads();   // all warps see completed buffer; zbuf safe to rewrite

        const ulonglong2* h2 =
            (const ulonglong2*)(hbuf + p * HBSTR + half * HPAD);
        unsigned long long a0 = 0ull, a1 = 0ull;
#pragma unroll
        for (int k = 0; k < 32; k++) {
            ulonglong2 hv = h2[k];
            fma2(a0, Wp[k].x, hv.x);
            fma2(a1, Wp[k].y, hv.y);
        }
        float2 f0 = *(float2*)&a0;
        float2 f1 = *(float2*)&a1;
        float acc = (f0.x + f0.y) + (f1.x + f1.y);
        acc += __shfl_xor_sync(0xffffffffu, acc, 1);   // combine column halves
        if (!half) zbuf[rr] = acc + xwreg;

        // prefetch next step's xw
        if (!half && tn < SQ) {
            int pos = dir ? (SQ - 1 - tn) : tn;
            xwreg = xw[(size_t)pos * NG + grow];
        }
        __syncthreads();   // zbuf ready

        if (tid < 32) {
            float zi = zbuf[tid], zf = zbuf[32 + tid];
            float zg = zbuf[64 + tid], zo = zbuf[96 + tid];
            float ig = sigm_f(zi);
            float fg = sigm_f(zf);
            float gg = tanh_f(zg);
            float og = sigm_f(zo);
            c = fmaf(fg, c, ig * gg);
            float hn = og * tanh_f(c);

            if (tn < SQ) {
                // pair-pack: even lane sends (own, odd partner) as one b64
                float ho = __shfl_xor_sync(0xffffffffu, hn, 1);
                if ((tid & 1) == 0) {
                    unsigned long long pv =
                        ((unsigned long long)__float_as_uint(ho) << 32) |
                        (unsigned long long)__float_as_uint(hn);
                    uint32_t bo  = (uint32_t)((p ^ 1) * HBSTR * 4);
                    uint32_t mbo = (uint32_t)((p ^ 1) * 8);
#pragma unroll
                    for (int rk = 0; rk < CL; rk++)
                        st_async_b64(rh[rk] + bo, pv, rmb[rk] + mbo);
                }
            }

            // off the latency-critical path: result store to global
            int pos = dir ? (SQ - 1 - t) : t;
            g_h[dir][(size_t)pos * HDIRD + r * 32 + tid] = hn;
        }
        // NO cluster.sync: next iteration's mbar_wait provides ordering.
    }
    CLUSTER_SYNC_();   // keep SMEM alive until all peers are done
}

// ---------------- kernel 4: feats = [h_f | h_b] @ Wout^T + b (warp per s) ----------------
__global__ void feats_k(const float* __restrict__ Wout, const float* __restrict__ bout) {
    __shared__ float Wsm[TAGS][512];
    __shared__ float bsm[TAGS];
    int tid = threadIdx.x;
    for (int i = tid; i < TAGS * 512; i += 256) Wsm[i / 512][i % 512] = Wout[i];
    if (tid < TAGS) bsm[tid] = bout[tid];
    __syncthreads();

    int lane = tid & 31;
    int s = blockIdx.x * 8 + (tid >> 5);     // warp per sequence position
    float acc[TAGS];
#pragma unroll
    for (int t = 0; t < TAGS; t++) acc[t] = 0.0f;

#pragma unroll
    for (int d = 0; d < 2; d++) {
        const float* hrow = (d == 0) ? &g_h[0][(size_t)s * HDIRD]
                                     : &g_h[1][(size_t)s * HDIRD];
#pragma unroll
        for (int k0 = 0; k0 < HDIRD; k0 += 32) {
            float x = hrow[k0 + lane];
#pragma unroll
            for (int t = 0; t < TAGS; t++)
                acc[t] = fmaf(x, Wsm[t][d * 256 + k0 + lane], acc[t]);
        }
    }
#pragma unroll
    for (int t = 0; t < TAGS; t++) {
#pragma unroll
        for (int o = 16; o > 0; o >>= 1) acc[t] += __shfl_xor_sync(0xffffffffu, acc[t], o);
    }
    if (lane == 0) {
#pragma unroll
        for (int t = 0; t < TAGS; t++) g_feats[s * TAGS + t] = acc[t] + bsm[t];
    }
}

// ---------------- kernel 5: Viterbi decode (single warp) ----------------
__global__ void viterbi_k(const float* __restrict__ trans, float* __restrict__ out,
                          int out_size) {
    __shared__ unsigned char bp[SQ][TAGS];   // 40 KB backpointers
    int n = threadIdx.x;

    float tr[TAGS];
#pragma unroll
    for (int p = 0; p < TAGS; p++) tr[p] = (n < TAGS) ? trans[n * TAGS + p] : NEGV;

    float fvr = (n == 8) ? 0.0f : NEGV;      // START = 8
    float fa = (n < TAGS) ? g_feats[0 * TAGS + n] : 0.0f;
    float fb = (n < TAGS) ? g_feats[1 * TAGS + n] : 0.0f;

    for (int t = 0; t < SQ; t++) {
        float m = -3.4e38f;
        int bi = 0;
#pragma unroll
        for (int p = 0; p < TAGS; p++) {
            float v = __shfl_sync(0xffffffffu, fvr, p) + tr[p];
            if (v > m) { m = v; bi = p; }    // strict > keeps first max (jnp.argmax)
        }
        if (n < TAGS) bp[t][n] = (unsigned char)bi;
        float nf = m + fa;
        fa = fb;
        int tn = t + 2;
        if (n < TAGS && tn < SQ) fb = g_feats[tn * TAGS + n];
        fvr = nf;
    }

    float term = fvr + ((n < TAGS) ? trans[9 * TAGS + n] : NEGV);
    float bm = -3.4e38f;
    int bidx = 0;
#pragma unroll
    for (int p = 0; p < TAGS; p++) {
        float v = __shfl_sync(0xffffffffu, term, p);
        if (v > bm) { bm = v; bidx = p; }
    }
    if (n == 0) {
        int off = (out_size > SQ) ? 1 : 0;
        if (off) out[0] = bm;                // score first, then path
        int tag = bidx;
        for (int t = SQ - 1; t >= 0; t--) {
            out[off + t] = (float)tag;
            tag = bp[t][tag];
        }
    }
}

// ---------------- launch ----------------
extern "C" void kernel_launch(void* const* d_in, const int* in_sizes, int n_in,
                              void* d_out, int out_size) {
    const int*   sent  = (const int*)d_in[0];
    const float* emb   = (const float*)d_in[1];
    const float* Wih_f = (const float*)d_in[2];
    const float* Whh_f = (const float*)d_in[3];
    const float* bih_f = (const float*)d_in[4];
    const float* bhh_f = (const float*)d_in[5];
    const float* Wih_b = (const float*)d_in[6];
    const float* Whh_b = (const float*)d_in[7];
    const float* bih_b = (const float*)d_in[8];
    const float* bhh_b = (const float*)d_in[9];
    const float* W_out = (const float*)d_in[10];
    const float* b_out = (const float*)d_in[11];
    const float* trans = (const float*)d_in[12];
    float* out = (float*)d_out;

    gather_k<<<(SQ * 64) / 256, 256>>>(sent, emb);
    xw_gemm_k<<<dim3(SQ / 64, NG / 64, 2), 256>>>(Wih_f, Wih_b, bih_f, bhh_f, bih_b, bhh_b);
    lstm_k<<<dim3(CL, 2, 1), 256>>>(Whh_f, Whh_b);
    feats_k<<<SQ / 8, 256>>>(W_out, b_out);   // 512 blocks x 8 warps = 4096 positions
    viterbi_k<<<1, 32>>>(trans, out, out_size);
}

// round 14
// speedup vs baseline: 1.2788x; 1.0116x over previous
#include <cuda_runtime.h>
#include <cstdint>

// ---------------- problem constants ----------------
#define SQ    4096          // sequence length
#define EMBD  256
#define HDIRD 256           // HID/2
#define NG    1024          // 4*HDIR
#define TAGS  10
#define NEGV  -10000.0f
#define CL    8             // cluster size per direction
#define HPAD  132           // padded half stride in floats (128+4 -> halves in different banks)
#define HBSTR 264           // one buffer = 2 halves = 264 floats

// ---------------- scratch (device globals; no dynamic alloc) ----------------
__device__ float g_x[SQ * EMBD];              // gathered embeddings   4 MB
__device__ float g_xw[2][SQ * NG];            // input-gate precompute 32 MB
__device__ float g_h[2][SQ * HDIRD];          // hidden states         8 MB
__device__ float g_feats[SQ * TAGS];          // CRF emission feats

// ---------------- helpers ----------------
__device__ __forceinline__ uint32_t smem_u32(const void* p) {
    return (uint32_t)__cvta_generic_to_shared(p);
}
__device__ __forceinline__ uint32_t mapa_u32(uint32_t laddr, uint32_t rank) {
    uint32_t rem;
    asm("mapa.shared::cluster.u32 %0, %1, %2;" : "=r"(rem) : "r"(laddr), "r"(rank));
    return rem;
}
// remote store with completion tx delivered to the DESTINATION CTA's mbarrier
__device__ __forceinline__ void st_async_f32(uint32_t raddr, float v, uint32_t rmbar) {
    asm volatile(
        "st.async.shared::cluster.mbarrier::complete_tx::bytes.b32 [%0], %1, [%2];"
        :: "r"(raddr), "r"(__float_as_uint(v)), "r"(rmbar) : "memory");
}
__device__ __forceinline__ void mbar_init(uint32_t a, uint32_t cnt) {
    asm volatile("mbarrier.init.shared.b64 [%0], %1;" :: "r"(a), "r"(cnt) : "memory");
}
__device__ __forceinline__ void mbar_expect_tx(uint32_t a, uint32_t bytes) {
    asm volatile("mbarrier.arrive.expect_tx.shared.b64 _, [%0], %1;"
                 :: "r"(a), "r"(bytes) : "memory");
}
// exact known-good wait form from ptx_helpers.cuh (local CTA scope)
__device__ __forceinline__ void mbar_wait(uint32_t a, uint32_t par) {
    uint32_t done;
    asm volatile(
        "{\n\t.reg .pred p;\n\t"
        "mbarrier.try_wait.parity.acquire.cta.shared::cta.b64 p, [%1], %2;\n\t"
        "selp.b32 %0, 1, 0, p;\n\t}"
        : "=r"(done) : "r"(a), "r"(par) : "memory");
    if (!done) {
        asm volatile(
            "{\n\t.reg .pred P1;\n\t"
            "WAIT_LOOP_%=:\n\t"
            "mbarrier.try_wait.parity.acquire.cta.shared::cta.b64 P1, [%0], %1, 0x989680;\n\t"
            "@P1 bra.uni WAIT_DONE_%=;\n\t"
            "bra.uni WAIT_LOOP_%=;\n\t"
            "WAIT_DONE_%=:\n\t}"
            :: "r"(a), "r"(par) : "memory");
    }
}
#define CLUSTER_SYNC_() do {                                                   \
    asm volatile("barrier.cluster.arrive.aligned;" ::: "memory");              \
    asm volatile("barrier.cluster.wait.aligned;"   ::: "memory");              \
} while (0)

__device__ __forceinline__ void fma2(unsigned long long& d,
                                     unsigned long long a, unsigned long long b) {
    asm("fma.rn.f32x2 %0, %1, %2, %0;" : "+l"(d) : "l"(a), "l"(b));
}

__device__ __forceinline__ float sigm_f(float x) {
    return 1.0f / (1.0f + __expf(-x));
}
__device__ __forceinline__ float tanh_f(float x) {
    float e = __expf(-2.0f * fabsf(x));
    float r = (1.0f - e) / (1.0f + e);
    return copysignf(r, x);
}

// ---------------- kernel 1: embedding gather ----------------
__global__ void gather_k(const int* __restrict__ sent, const float* __restrict__ emb) {
    int gid = blockIdx.x * blockDim.x + threadIdx.x;  // over SQ*64 float4
    int row = gid >> 6;
    int c   = gid & 63;
    ((float4*)g_x)[row * 64 + c] =
        ((const float4*)emb)[(size_t)sent[row] * 64 + c];
}

// ---------------- kernel 2: xw = x @ Wih^T + (bih+bhh), both directions ----------------
__global__ void xw_gemm_k(const float* __restrict__ Wf, const float* __restrict__ Wb,
                          const float* __restrict__ bihf, const float* __restrict__ bhhf,
                          const float* __restrict__ bihb, const float* __restrict__ bhhb) {
    int d = blockIdx.z;
    const float* W  = d ? Wb : Wf;
    const float* b1 = d ? bihb : bihf;
    const float* b2 = d ? bhhb : bhhf;

    __shared__ float As[32][65];
    __shared__ float Bs[32][65];

    int s0 = blockIdx.x * 64;
    int j0 = blockIdx.y * 64;
    int tid = threadIdx.x;
    int tx = tid & 15, ty = tid >> 4;

    float acc[4][4];
#pragma unroll
    for (int i = 0; i < 4; i++)
#pragma unroll
        for (int j = 0; j < 4; j++) acc[i][j] = 0.0f;

    for (int k0 = 0; k0 < EMBD; k0 += 32) {
#pragma unroll
        for (int i = 0; i < 8; i++) {
            int idx = i * 256 + tid;
            int si = idx >> 5, e = idx & 31;
            As[e][si] = g_x[(s0 + si) * EMBD + k0 + e];
            Bs[e][si] = W[(j0 + si) * EMBD + k0 + e];
        }
        __syncthreads();
#pragma unroll
        for (int e = 0; e < 32; e++) {
            float a[4], bb[4];
#pragma unroll
            for (int i = 0; i < 4; i++) { a[i] = As[e][ty * 4 + i]; bb[i] = Bs[e][tx * 4 + i]; }
#pragma unroll
            for (int i = 0; i < 4; i++)
#pragma unroll
                for (int j = 0; j < 4; j++) acc[i][j] = fmaf(a[i], bb[j], acc[i][j]);
        }
        __syncthreads();
    }
#pragma unroll
    for (int i = 0; i < 4; i++)
#pragma unroll
        for (int j = 0; j < 4; j++) {
            int jj = j0 + tx * 4 + j;
            g_xw[d][(s0 + ty * 4 + i) * NG + jj] = acc[i][j] + b1[jj] + b2[jj];
        }
}

// ---------------- kernel 3: recurrent LSTM, one 8-CTA cluster per direction ----------------
// R10 protocol (scalar st.async + expect_tx 1024 B/phase + local acquire waits),
// with the first per-step __syncthreads REMOVED — it is redundant:
//  * hbuf visibility: every thread executes mbar_wait (per-thread acquire).
//  * zbuf anti-dep: warp0 reads zbuf before its sends; other warps can only
//    rewrite zbuf next step after passing their wait, which needs those sends.
//  * expect-before-own-sends: both are warp0 program order (tid0 posts, tid<32 send).
__global__ void __cluster_dims__(CL, 1, 1) __launch_bounds__(256, 1)
lstm_k(const float* __restrict__ Whhf, const float* __restrict__ Whhb) {
    int dir = blockIdx.y;
    const float* Whh = dir ? Whhb : Whhf;
    const float* xw  = g_xw[dir];
    int r   = blockIdx.x;           // cluster rank
    int tid = threadIdx.x;
    int rr   = tid >> 1;            // 0..127 local row
    int half = tid & 1;             // column half
    int gate = rr >> 5;
    int j5   = rr & 31;
    int grow = gate * HDIRD + r * 32 + j5;   // global Whh row / xw column

    // weights -> registers, packed as f32 pairs (half row = 128 cols)
    ulonglong2 Wp[32];
    const ulonglong2* wsrc =
        (const ulonglong2*)(Whh + (size_t)grow * HDIRD + half * 128);
#pragma unroll
    for (int k = 0; k < 32; k++) Wp[k] = wsrc[k];

    __shared__ __align__(16) float hbuf[2 * HBSTR];   // halves padded by 16B
    __shared__ float zbuf[128];
    __shared__ __align__(8) unsigned long long mbs[2]; // mbar per buffer

    for (int i = tid; i < 2 * HBSTR; i += 256) hbuf[i] = 0.0f;
    uint32_t mbb = smem_u32(mbs);
    if (tid == 0) {
        mbar_init(mbb + 0, 1);
        mbar_init(mbb + 8, 1);
    }
    __syncthreads();
    CLUSTER_SYNC_();   // zeroed hbuf + initialized mbarriers visible cluster-wide

    // hoisted remote addresses (used by tid<32): data slot + destination mbar
    uint32_t hb0 = smem_u32(hbuf);
    uint32_t hoff4 = (uint32_t)(r * 32 + (tid & 31) + ((r >= 4) ? 4 : 0)) * 4u;
    uint32_t rh[CL], rmb[CL];
#pragma unroll
    for (int rk = 0; rk < CL; rk++) {
        rh[rk]  = mapa_u32(hb0, rk) + hoff4;
        rmb[rk] = mapa_u32(mbb, rk);
    }

    float c = 0.0f;
    float xwreg = 0.0f;
    int pos0 = dir ? (SQ - 1) : 0;
    if (!half) xwreg = xw[(size_t)pos0 * NG + grow];

    for (int t = 0; t < SQ; t++) {
        int p = t & 1;
        int tn = t + 1;

        // post this phase's expectation for the buffer being filled (p^1)
        if (tid == 0 && tn < SQ)
            mbar_expect_tx(mbb + (uint32_t)((p ^ 1) * 8), 1024u);
        // wait for buffer p to be complete (skip first step: zero-initialized)
        if (t) mbar_wait(mbb + (uint32_t)(p * 8), (uint32_t)(((t - 1) >> 1) & 1));
        // (no __syncthreads here — see kernel comment)

        const ulonglong2* h2 =
            (const ulonglong2*)(hbuf + p * HBSTR + half * HPAD);
        unsigned long long a0 = 0ull, a1 = 0ull;
#pragma unroll
        for (int k = 0; k < 32; k++) {
            ulonglong2 hv = h2[k];
            fma2(a0, Wp[k].x, hv.x);
            fma2(a1, Wp[k].y, hv.y);
        }
        float2 f0 = *(float2*)&a0;
        float2 f1 = *(float2*)&a1;
        float acc = (f0.x + f0.y) + (f1.x + f1.y);
        acc += __shfl_xor_sync(0xffffffffu, acc, 1);   // combine column halves
        if (!half) zbuf[rr] = acc + xwreg;

        // prefetch next step's xw
        if (!half && tn < SQ) {
            int pos = dir ? (SQ - 1 - tn) : tn;
            xwreg = xw[(size_t)pos * NG + grow];
        }
        __syncthreads();   // zbuf ready for the gate warp

        if (tid < 32) {
            float zi = zbuf[tid], zf = zbuf[32 + tid];
            float zg = zbuf[64 + tid], zo = zbuf[96 + tid];
            float ig = sigm_f(zi);
            float fg = sigm_f(zf);
            float gg = tanh_f(zg);
            float og = sigm_f(zo);
            c = fmaf(fg, c, ig * gg);
            float hn = og * tanh_f(c);

            if (tn < SQ) {   // data + completion to every rank (self included)
                uint32_t bo  = (uint32_t)((p ^ 1) * HBSTR * 4);
                uint32_t mbo = (uint32_t)((p ^ 1) * 8);
#pragma unroll
                for (int rk = 0; rk < CL; rk++)
                    st_async_f32(rh[rk] + bo, hn, rmb[rk] + mbo);
            }

            // off the latency-critical path: result store to global
            int pos = dir ? (SQ - 1 - t) : t;
            g_h[dir][(size_t)pos * HDIRD + r * 32 + tid] = hn;
        }
        // NO cluster.sync: next iteration's mbar_wait provides ordering.
    }
    CLUSTER_SYNC_();   // keep SMEM alive until all peers are done
}

// ---------------- kernel 4: feats = [h_f | h_b] @ Wout^T + b (warp per s) ----------------
__global__ void feats_k(const float* __restrict__ Wout, const float* __restrict__ bout) {
    __shared__ float Wsm[TAGS][512];
    __shared__ float bsm[TAGS];
    int tid = threadIdx.x;
    for (int i = tid; i < TAGS * 512; i += 256) Wsm[i / 512][i % 512] = Wout[i];
    if (tid < TAGS) bsm[tid] = bout[tid];
    __syncthreads();

    int lane = tid & 31;
    int s = blockIdx.x * 8 + (tid >> 5);     // warp per sequence position
    float acc[TAGS];
#pragma unroll
    for (int t = 0; t < TAGS; t++) acc[t] = 0.0f;

#pragma unroll
    for (int d = 0; d < 2; d++) {
        const float* hrow = (d == 0) ? &g_h[0][(size_t)s * HDIRD]
                                     : &g_h[1][(size_t)s * HDIRD];
#pragma unroll
        for (int k0 = 0; k0 < HDIRD; k0 += 32) {
            float x = hrow[k0 + lane];
#pragma unroll
            for (int t = 0; t < TAGS; t++)
                acc[t] = fmaf(x, Wsm[t][d * 256 + k0 + lane], acc[t]);
        }
    }
#pragma unroll
    for (int t = 0; t < TAGS; t++) {
#pragma unroll
        for (int o = 16; o > 0; o >>= 1) acc[t] += __shfl_xor_sync(0xffffffffu, acc[t], o);
    }
    if (lane == 0) {
#pragma unroll
        for (int t = 0; t < TAGS; t++) g_feats[s * TAGS + t] = acc[t] + bsm[t];
    }
}

// ---------------- kernel 5: Viterbi decode (single warp) ----------------
__global__ void viterbi_k(const float* __restrict__ trans, float* __restrict__ out,
                          int out_size) {
    __shared__ unsigned char bp[SQ][TAGS];   // 40 KB backpointers
    int n = threadIdx.x;

    float tr[TAGS];
#pragma unroll
    for (int p = 0; p < TAGS; p++) tr[p] = (n < TAGS) ? trans[n * TAGS + p] : NEGV;

    float fvr = (n == 8) ? 0.0f : NEGV;      // START = 8
    float fa = (n < TAGS) ? g_feats[0 * TAGS + n] : 0.0f;
    float fb = (n < TAGS) ? g_feats[1 * TAGS + n] : 0.0f;

    for (int t = 0; t < SQ; t++) {
        float m = -3.4e38f;
        int bi = 0;
#pragma unroll
        for (int p = 0; p < TAGS; p++) {
            float v = __shfl_sync(0xffffffffu, fvr, p) + tr[p];
            if (v > m) { m = v; bi = p; }    // strict > keeps first max (jnp.argmax)
        }
        if (n < TAGS) bp[t][n] = (unsigned char)bi;
        float nf = m + fa;
        fa = fb;
        int tn = t + 2;
        if (n < TAGS && tn < SQ) fb = g_feats[tn * TAGS + n];
        fvr = nf;
    }

    float term = fvr + ((n < TAGS) ? trans[9 * TAGS + n] : NEGV);
    float bm = -3.4e38f;
    int bidx = 0;
#pragma unroll
    for (int p = 0; p < TAGS; p++) {
        float v = __shfl_sync(0xffffffffu, term, p);
        if (v > bm) { bm = v; bidx = p; }
    }
    if (n == 0) {
        int off = (out_size > SQ) ? 1 : 0;
        if (off) out[0] = bm;                // score first, then path
        int tag = bidx;
        for (int t = SQ - 1; t >= 0; t--) {
            out[off + t] = (float)tag;
            tag = bp[t][tag];
        }
    }
}

// ---------------- launch ----------------
extern "C" void kernel_launch(void* const* d_in, const int* in_sizes, int n_in,
                              void* d_out, int out_size) {
    const int*   sent  = (const int*)d_in[0];
    const float* emb   = (const float*)d_in[1];
    const float* Wih_f = (const float*)d_in[2];
    const float* Whh_f = (const float*)d_in[3];
    const float* bih_f = (const float*)d_in[4];
    const float* bhh_f = (const float*)d_in[5];
    const float* Wih_b = (const float*)d_in[6];
    const float* Whh_b = (const float*)d_in[7];
    const float* bih_b = (const float*)d_in[8];
    const float* bhh_b = (const float*)d_in[9];
    const float* W_out = (const float*)d_in[10];
    const float* b_out = (const float*)d_in[11];
    const float* trans = (const float*)d_in[12];
    float* out = (float*)d_out;

    gather_k<<<(SQ * 64) / 256, 256>>>(sent, emb);
    xw_gemm_k<<<dim3(SQ / 64, NG / 64, 2), 256>>>(Wih_f, Wih_b, bih_f, bhh_f, bih_b, bhh_b);
    lstm_k<<<dim3(CL, 2, 1), 256>>>(Whh_f, Whh_b);
    feats_k<<<SQ / 8, 256>>>(W_out, b_out);   // 512 blocks x 8 warps = 4096 positions
    viterbi_k<<<1, 32>>>(trans, out, out_size);
}